// round 9
// baseline (speedup 1.0000x reference)
#include <cuda_runtime.h>
#include <cstdint>

#define MM 2
#define LL 6
#define NN 512
#define HH 64
#define VK 1.0f
#define SIG2 0.01
#define DDIM 2.0
#define NT 8192
#define RMAX 16.0f
#define HSTEP (RMAX / (float)NT)
#define NWARP (MM * LL * NN)      // 6144 i-warps total

typedef unsigned long long u64;

__device__ float4 g_raw[NT + 64];   // (phi+b3, dphi, d2phi, 0) at nodes 0..NT
__device__ float4 g_tab[NT];        // (phi, dphi, d2, d2-slope) Taylor entries
__device__ double g_slots[64];
__device__ unsigned g_cnt;

__device__ __forceinline__ float tanh_fast(float x) {
    float y; asm("tanh.approx.f32 %0, %1;" : "=f"(y) : "f"(x)); return y;
}
__device__ __forceinline__ u64 pack2(float x) {
    u64 r; asm("mov.b64 %0, {%1,%1};" : "=l"(r) : "f"(x)); return r;
}
__device__ __forceinline__ u64 pack2f(float lo, float hi) {
    u64 r; asm("mov.b64 %0, {%1,%2};" : "=l"(r) : "f"(lo), "f"(hi)); return r;
}
__device__ __forceinline__ void unpack2(u64 v, float& lo, float& hi) {
    asm("mov.b64 {%0,%1}, %2;" : "=f"(lo), "=f"(hi) : "l"(v));
}
__device__ __forceinline__ u64 fma2(u64 a, u64 b, u64 c) {
    u64 d; asm("fma.rn.f32x2 %0, %1, %2, %3;" : "=l"(d) : "l"(a), "l"(b), "l"(c)); return d;
}

// ------- builder: 4 lanes per node, each lane 16 of 64 output channels -------
__global__ void __launch_bounds__(256)
build_table(const float* __restrict__ w1, const float* __restrict__ b1,
            const float* __restrict__ W2, const float* __restrict__ b2,
            const float* __restrict__ w3, const float* __restrict__ b3p)
{
    __shared__ float sW2[HH * HH];
    __shared__ float sw1[HH], sb1[HH], sb2[HH], sw3[HH];
    __shared__ float h1s[HH * 64];      // [k][node], 64 nodes per block

    int tid = threadIdx.x;
    #pragma unroll
    for (int s = 0; s < HH * HH; s += 256) sW2[s + tid] = W2[s + tid];
    if (tid < HH) { sw1[tid] = w1[tid]; sb1[tid] = b1[tid]; sb2[tid] = b2[tid]; sw3[tid] = w3[tid]; }

    if (blockIdx.x == 0) {
        if (tid < 64) g_slots[tid] = 0.0;
        if (tid == 64) g_cnt = 0u;
    }
    __syncthreads();

    int node = tid >> 2;                 // 0..63 within block
    int quarter = tid & 3;               // 0..3
    int ridx = blockIdx.x * 64 + node;   // global node id (guarded at write)
    float r = (float)ridx * HSTEP;

    // layer 1: each lane computes 16 of 64 h1 channels
    int kbase = quarter * 16;
    #pragma unroll 8
    for (int k = kbase; k < kbase + 16; k++)
        h1s[k * 64 + node] = tanh_fast(fmaf(r, sw1[k], sb1[k]));
    __syncthreads();

    float phi = 0.f, dphi = 0.f, d2phi = 0.f;
    {
        int c = quarter * 16;
        u64 z2[8], zp[8], zpp[8];
        #pragma unroll
        for (int p = 0; p < 8; p++) {
            z2[p]  = pack2f(sb2[c + 2 * p], sb2[c + 2 * p + 1]);
            zp[p]  = 0ull;
            zpp[p] = 0ull;
        }
        #pragma unroll 4
        for (int k = 0; k < HH; k++) {
            float h   = h1s[k * 64 + node];
            float w1k = sw1[k];
            float s   = fmaf(-h, h, 1.f);
            float hp  = s * w1k;
            float hpp = -2.f * h * hp * w1k;
            u64 hh   = pack2(h);
            u64 hpx  = pack2(hp);
            u64 hppx = pack2(hpp);
            const ulonglong2* wr = (const ulonglong2*)(sW2 + k * HH + c);
            #pragma unroll
            for (int q = 0; q < 4; q++) {
                ulonglong2 w = wr[q];
                z2[2 * q]      = fma2(w.x, hh,   z2[2 * q]);
                z2[2 * q + 1]  = fma2(w.y, hh,   z2[2 * q + 1]);
                zp[2 * q]      = fma2(w.x, hpx,  zp[2 * q]);
                zp[2 * q + 1]  = fma2(w.y, hpx,  zp[2 * q + 1]);
                zpp[2 * q]     = fma2(w.x, hppx, zpp[2 * q]);
                zpp[2 * q + 1] = fma2(w.y, hppx, zpp[2 * q + 1]);
            }
        }
        #pragma unroll
        for (int p = 0; p < 8; p++) {
            float a0, a1, p0, p1, q0, q1;
            unpack2(z2[p], a0, a1);
            unpack2(zp[p], p0, p1);
            unpack2(zpp[p], q0, q1);
            float w30 = sw3[c + 2 * p], w31 = sw3[c + 2 * p + 1];

            float h2 = tanh_fast(a0);
            phi = fmaf(w30, h2, phi);
            float e   = fmaf(-h2, h2, 1.f);
            float hp2 = e * p0;
            float hq2 = fmaf(e, q0, -2.f * h2 * hp2 * p0);
            dphi  = fmaf(w30, hp2, dphi);
            d2phi = fmaf(w30, hq2, d2phi);

            h2 = tanh_fast(a1);
            phi = fmaf(w31, h2, phi);
            e   = fmaf(-h2, h2, 1.f);
            hp2 = e * p1;
            hq2 = fmaf(e, q1, -2.f * h2 * hp2 * p1);
            dphi  = fmaf(w31, hp2, dphi);
            d2phi = fmaf(w31, hq2, d2phi);
        }
    }

    // combine the 4 quarter-lanes
    #pragma unroll
    for (int s = 1; s <= 2; s <<= 1) {
        phi   += __shfl_xor_sync(0xffffffffu, phi,   s);
        dphi  += __shfl_xor_sync(0xffffffffu, dphi,  s);
        d2phi += __shfl_xor_sync(0xffffffffu, d2phi, s);
    }

    if (quarter == 0 && ridx <= NT)
        g_raw[ridx] = make_float4(phi + b3p[0], dphi, d2phi, 0.f);
}

// ------- pack: Taylor entries (phi, dphi, d2, d2_{i+1}-d2_i) -------
__global__ void __launch_bounds__(256)
pack_table()
{
    int i = blockIdx.x * 256 + threadIdx.x;
    if (i < NT) {
        float4 a = g_raw[i];
        float4 b = g_raw[i + 1];
        g_tab[i] = make_float4(a.x, a.y, a.z, b.z - a.z);
    }
}

// ------- pair pass: one warp per i, fused final reduction -------
__global__ void __launch_bounds__(256)
pair_pass(const float* __restrict__ data, const float* __restrict__ t,
          float* __restrict__ out)
{
    __shared__ float2 sx[NN];

    int tid  = threadIdx.x;
    int w    = tid >> 5;
    int lane = tid & 31;
    int sl   = blockIdx.x >> 6;          // 0..11
    int i    = (blockIdx.x & 63) * 8 + w;
    int l    = sl % LL;
    int m    = sl / LL;
    bool deriv   = (l < LL - 1);
    bool needphi = (l == 0 || l == LL - 1);

    const float2* snap = (const float2*)(data + ((size_t)(m * LL + l)) * NN * 2);
    sx[tid]       = snap[tid];
    sx[tid + 256] = snap[tid + 256];
    __syncthreads();

    float2 xi = sx[i];
    float gx = 0.f, gy = 0.f, lap = 0.f, phis = 0.f;
    const float scale = (float)NT / RMAX;

    #pragma unroll 8
    for (int jj = 0; jj < 16; jj++) {
        int j = lane + jj * 32;
        float2 xj = sx[j];
        float dx = xi.x - xj.x, dy = xi.y - xj.y;
        float ssq = dx * dx + dy * dy;
        if (j != i) {
            float inv = rsqrtf(fmaxf(ssq, 1e-20f));
            float r = ssq * inv;
            float u = r * scale;
            int i0 = (int)u;
            i0 = (i0 > NT - 2) ? (NT - 2) : i0;
            float f = u - (float)i0;
            float4 e = __ldg(&g_tab[i0]);
            float x  = f * HSTEP;
            float d2 = fmaf(f, e.w, e.z);
            float dp = fmaf(x, fmaf(0.5f * f, e.w, e.z), e.y);
            float ph = fmaf(x, fmaf(0.5f * x, fmaf(0.33333333f * f, e.w, e.z), e.y), e.x);
            phis += ph;
            lap  += d2;
            float c = dp * inv;
            gx = fmaf(c, dx, gx);
            gy = fmaf(c, dy, gy);
        }
    }

    #pragma unroll
    for (int s = 16; s > 0; s >>= 1) {
        gx   += __shfl_xor_sync(0xffffffffu, gx,   s);
        gy   += __shfl_xor_sync(0xffffffffu, gy,   s);
        lap  += __shfl_xor_sync(0xffffffffu, lap,  s);
        phis += __shfl_xor_sync(0xffffffffu, phis, s);
    }

    unsigned old = 0u;
    if (lane == 0) {
        double contrib = 0.0;
        if (deriv) {
            float dtl = t[l + 1] - t[l];
            float dgx = fmaf(-VK, xi.x, -gx / NN);
            float dgy = fmaf(-VK, xi.y, -gy / NN);
            contrib += (double)dtl * ((double)dgx * dgx + (double)dgy * dgy) / NN;
            contrib += SIG2 * (double)dtl * ((double)lap / NN) / NN;
        }
        if (needphi) {
            double sign = (l == 0) ? 2.0 : -2.0;
            contrib += sign * ((double)phis / ((double)NN * NN)
                             + 0.5 * (double)VK * ((double)xi.x * xi.x + (double)xi.y * xi.y) / NN);
        }
        atomicAdd(&g_slots[i & 63], contrib);
        __threadfence();
        old = atomicAdd(&g_cnt, 1u);
    }
    old = __shfl_sync(0xffffffffu, old, 0);

    if (old == (unsigned)(NWARP - 1)) {
        __threadfence();
        double s = *((volatile double*)&g_slots[lane])
                 + *((volatile double*)&g_slots[lane + 32]);
        #pragma unroll
        for (int k = 16; k > 0; k >>= 1) {
            double other;
            {
                u64 v = __double_as_longlong(s);
                uint32_t lo = (uint32_t)v, hi = (uint32_t)(v >> 32);
                lo = __shfl_xor_sync(0xffffffffu, lo, k);
                hi = __shfl_xor_sync(0xffffffffu, hi, k);
                other = __longlong_as_double(((u64)hi << 32) | lo);
            }
            s += other;
        }
        if (lane == 0) {
            s += (double)MM * SIG2 * (double)VK * DDIM * (double)(t[LL - 1] - t[0]);
            double res = s / (double)(MM * (LL - 1));
            out[0] = (float)(res * res);
        }
    }
}

extern "C" void kernel_launch(void* const* d_in, const int* in_sizes, int n_in,
                              void* d_out, int out_size)
{
    const float* data = (const float*)d_in[0];
    const float* t    = (const float*)d_in[1];
    const float* w1   = (const float*)d_in[2];
    const float* b1   = (const float*)d_in[3];
    const float* W2   = (const float*)d_in[4];
    const float* b2   = (const float*)d_in[5];
    const float* w3   = (const float*)d_in[6];
    const float* b3   = (const float*)d_in[7];

    build_table<<<(NT + 64) / 64, 256>>>(w1, b1, W2, b2, w3, b3);
    pack_table<<<NT / 256, 256>>>();
    pair_pass<<<12 * 64, 256>>>(data, t, (float*)d_out);
}

// round 10
// speedup vs baseline: 1.1209x; 1.1209x over previous
#include <cuda_runtime.h>
#include <cstdint>

#define MM 2
#define LL 6
#define NN 512
#define HH 64
#define VK 1.0f
#define SIG2 0.01
#define DDIM 2.0
#define NT 8192
#define RMAX 16.0f
#define HSTEP (RMAX / (float)NT)
#define NWARP (MM * LL * NN)      // 6144 i-warps total
#define BNODES 64                 // nodes computed per builder block
#define BSTRIDE 63                // entries emitted per builder block (overlap 1)

typedef unsigned long long u64;

__device__ float4 g_tab[NT];        // (phi, dphi, d2, d2-slope) Taylor entries
__device__ double g_slots[64];
__device__ unsigned g_cnt;

__device__ __forceinline__ float tanh_fast(float x) {
    float y; asm("tanh.approx.f32 %0, %1;" : "=f"(y) : "f"(x)); return y;
}
__device__ __forceinline__ u64 pack2(float x) {
    u64 r; asm("mov.b64 %0, {%1,%1};" : "=l"(r) : "f"(x)); return r;
}
__device__ __forceinline__ u64 pack2f(float lo, float hi) {
    u64 r; asm("mov.b64 %0, {%1,%2};" : "=l"(r) : "f"(lo), "f"(hi)); return r;
}
__device__ __forceinline__ void unpack2(u64 v, float& lo, float& hi) {
    asm("mov.b64 {%0,%1}, %2;" : "=f"(lo), "=f"(hi) : "l"(v));
}
__device__ __forceinline__ u64 fma2(u64 a, u64 b, u64 c) {
    u64 d; asm("fma.rn.f32x2 %0, %1, %2, %3;" : "=l"(d) : "l"(a), "l"(b), "l"(c)); return d;
}

// ------- builder (R8 2-way split) + fused Taylor pack via smem overlap -------
__global__ void __launch_bounds__(128)
build_table(const float* __restrict__ w1, const float* __restrict__ b1,
            const float* __restrict__ W2, const float* __restrict__ b2,
            const float* __restrict__ w3, const float* __restrict__ b3p)
{
    __shared__ float sW2[HH * HH];
    __shared__ float sw1[HH], sb1[HH], sb2[HH], sw3[HH];
    __shared__ float h1s[HH * 64];        // [k][pair]
    __shared__ float sphi[BNODES], sdphi[BNODES], sd2[BNODES];

    int tid = threadIdx.x;
    #pragma unroll
    for (int s = 0; s < HH * HH; s += 128) sW2[s + tid] = W2[s + tid];
    if (tid < HH) { sw1[tid] = w1[tid]; sb1[tid] = b1[tid]; sb2[tid] = b2[tid]; sw3[tid] = w3[tid]; }

    if (blockIdx.x == 0) {
        if (tid < 64) g_slots[tid] = 0.0;
        if (tid == 64) g_cnt = 0u;
    }
    __syncthreads();

    int half = tid & 1;
    int pair = tid >> 1;                     // node slot 0..63
    int ridx = blockIdx.x * BSTRIDE + pair;  // global node id
    float r = (float)ridx * HSTEP;

    // layer 1 (split across the two lanes of the pair)
    int kbase = half * 32;
    #pragma unroll 8
    for (int k = kbase; k < kbase + 32; k++)
        h1s[k * 64 + pair] = tanh_fast(fmaf(r, sw1[k], sb1[k]));
    __syncthreads();

    float phi = 0.f, dphi = 0.f, d2phi = 0.f;

    #pragma unroll
    for (int cc = 0; cc < 2; cc++) {
        int c = half * 32 + cc * 16;
        u64 z2[8], zp[8], zpp[8];
        #pragma unroll
        for (int p = 0; p < 8; p++) {
            z2[p]  = pack2f(sb2[c + 2 * p], sb2[c + 2 * p + 1]);
            zp[p]  = 0ull;
            zpp[p] = 0ull;
        }
        #pragma unroll 8
        for (int k = 0; k < HH; k++) {
            float h   = h1s[k * 64 + pair];
            float w1k = sw1[k];
            float s   = fmaf(-h, h, 1.f);
            float hp  = s * w1k;
            float hpp = -2.f * h * hp * w1k;
            u64 hh   = pack2(h);
            u64 hpx  = pack2(hp);
            u64 hppx = pack2(hpp);
            const ulonglong2* wr = (const ulonglong2*)(sW2 + k * HH + c);
            #pragma unroll
            for (int q = 0; q < 4; q++) {
                ulonglong2 w = wr[q];
                z2[2 * q]      = fma2(w.x, hh,   z2[2 * q]);
                z2[2 * q + 1]  = fma2(w.y, hh,   z2[2 * q + 1]);
                zp[2 * q]      = fma2(w.x, hpx,  zp[2 * q]);
                zp[2 * q + 1]  = fma2(w.y, hpx,  zp[2 * q + 1]);
                zpp[2 * q]     = fma2(w.x, hppx, zpp[2 * q]);
                zpp[2 * q + 1] = fma2(w.y, hppx, zpp[2 * q + 1]);
            }
        }
        #pragma unroll
        for (int p = 0; p < 8; p++) {
            float a0, a1, p0, p1, q0, q1;
            unpack2(z2[p], a0, a1);
            unpack2(zp[p], p0, p1);
            unpack2(zpp[p], q0, q1);
            float w30 = sw3[c + 2 * p], w31 = sw3[c + 2 * p + 1];

            float h2 = tanh_fast(a0);
            phi = fmaf(w30, h2, phi);
            float e   = fmaf(-h2, h2, 1.f);
            float hp2 = e * p0;
            float hq2 = fmaf(e, q0, -2.f * h2 * hp2 * p0);
            dphi  = fmaf(w30, hp2, dphi);
            d2phi = fmaf(w30, hq2, d2phi);

            h2 = tanh_fast(a1);
            phi = fmaf(w31, h2, phi);
            e   = fmaf(-h2, h2, 1.f);
            hp2 = e * p1;
            hq2 = fmaf(e, q1, -2.f * h2 * hp2 * p1);
            dphi  = fmaf(w31, hp2, dphi);
            d2phi = fmaf(w31, hq2, d2phi);
        }
    }

    phi   += __shfl_xor_sync(0xffffffffu, phi,   1);
    dphi  += __shfl_xor_sync(0xffffffffu, dphi,  1);
    d2phi += __shfl_xor_sync(0xffffffffu, d2phi, 1);

    if (half == 0) {
        sphi[pair]  = phi + b3p[0];
        sdphi[pair] = dphi;
        sd2[pair]   = d2phi;
    }
    __syncthreads();

    // emit Taylor entries for the first 63 nodes of this block
    if (half == 0 && pair < BSTRIDE) {
        int e = blockIdx.x * BSTRIDE + pair;
        if (e < NT)
            g_tab[e] = make_float4(sphi[pair], sdphi[pair], sd2[pair],
                                   sd2[pair + 1] - sd2[pair]);
    }
}

// ------- pair pass: one warp per i, fused final reduction -------
__global__ void __launch_bounds__(256)
pair_pass(const float* __restrict__ data, const float* __restrict__ t,
          float* __restrict__ out)
{
    __shared__ float2 sx[NN];

    int tid  = threadIdx.x;
    int w    = tid >> 5;
    int lane = tid & 31;
    int sl   = blockIdx.x >> 6;          // 0..11
    int i    = (blockIdx.x & 63) * 8 + w;
    int l    = sl % LL;
    int m    = sl / LL;
    bool deriv   = (l < LL - 1);
    bool needphi = (l == 0 || l == LL - 1);

    const float2* snap = (const float2*)(data + ((size_t)(m * LL + l)) * NN * 2);
    sx[tid]       = snap[tid];
    sx[tid + 256] = snap[tid + 256];
    __syncthreads();

    float2 xi = sx[i];
    float gx = 0.f, gy = 0.f, lap = 0.f, phis = 0.f;
    const float scale = (float)NT / RMAX;

    #pragma unroll 8
    for (int jj = 0; jj < 16; jj++) {
        int j = lane + jj * 32;
        float2 xj = sx[j];
        float dx = xi.x - xj.x, dy = xi.y - xj.y;
        float ssq = dx * dx + dy * dy;
        if (j != i) {
            float inv = rsqrtf(fmaxf(ssq, 1e-20f));
            float r = ssq * inv;
            float u = r * scale;
            int i0 = (int)u;
            i0 = (i0 > NT - 2) ? (NT - 2) : i0;
            float f = u - (float)i0;
            float4 e = __ldg(&g_tab[i0]);
            float x  = f * HSTEP;
            float d2 = fmaf(f, e.w, e.z);
            float dp = fmaf(x, fmaf(0.5f * f, e.w, e.z), e.y);
            float ph = fmaf(x, fmaf(0.5f * x, fmaf(0.33333333f * f, e.w, e.z), e.y), e.x);
            phis += ph;
            lap  += d2;
            float c = dp * inv;
            gx = fmaf(c, dx, gx);
            gy = fmaf(c, dy, gy);
        }
    }

    #pragma unroll
    for (int s = 16; s > 0; s >>= 1) {
        gx   += __shfl_xor_sync(0xffffffffu, gx,   s);
        gy   += __shfl_xor_sync(0xffffffffu, gy,   s);
        lap  += __shfl_xor_sync(0xffffffffu, lap,  s);
        phis += __shfl_xor_sync(0xffffffffu, phis, s);
    }

    unsigned old = 0u;
    if (lane == 0) {
        double contrib = 0.0;
        if (deriv) {
            float dtl = t[l + 1] - t[l];
            float dgx = fmaf(-VK, xi.x, -gx / NN);
            float dgy = fmaf(-VK, xi.y, -gy / NN);
            contrib += (double)dtl * ((double)dgx * dgx + (double)dgy * dgy) / NN;
            contrib += SIG2 * (double)dtl * ((double)lap / NN) / NN;
        }
        if (needphi) {
            double sign = (l == 0) ? 2.0 : -2.0;
            contrib += sign * ((double)phis / ((double)NN * NN)
                             + 0.5 * (double)VK * ((double)xi.x * xi.x + (double)xi.y * xi.y) / NN);
        }
        atomicAdd(&g_slots[i & 63], contrib);
        __threadfence();
        old = atomicAdd(&g_cnt, 1u);
    }
    old = __shfl_sync(0xffffffffu, old, 0);

    if (old == (unsigned)(NWARP - 1)) {
        __threadfence();
        double s = *((volatile double*)&g_slots[lane])
                 + *((volatile double*)&g_slots[lane + 32]);
        #pragma unroll
        for (int k = 16; k > 0; k >>= 1) {
            double other;
            {
                u64 v = __double_as_longlong(s);
                uint32_t lo = (uint32_t)v, hi = (uint32_t)(v >> 32);
                lo = __shfl_xor_sync(0xffffffffu, lo, k);
                hi = __shfl_xor_sync(0xffffffffu, hi, k);
                other = __longlong_as_double(((u64)hi << 32) | lo);
            }
            s += other;
        }
        if (lane == 0) {
            s += (double)MM * SIG2 * (double)VK * DDIM * (double)(t[LL - 1] - t[0]);
            double res = s / (double)(MM * (LL - 1));
            out[0] = (float)(res * res);
        }
    }
}

extern "C" void kernel_launch(void* const* d_in, const int* in_sizes, int n_in,
                              void* d_out, int out_size)
{
    const float* data = (const float*)d_in[0];
    const float* t    = (const float*)d_in[1];
    const float* w1   = (const float*)d_in[2];
    const float* b1   = (const float*)d_in[3];
    const float* W2   = (const float*)d_in[4];
    const float* b2   = (const float*)d_in[5];
    const float* w3   = (const float*)d_in[6];
    const float* b3   = (const float*)d_in[7];

    int bgrid = (NT + BSTRIDE - 1) / BSTRIDE;   // 131 blocks (overlap by 1 node)
    build_table<<<bgrid, 128>>>(w1, b1, W2, b2, w3, b3);
    pair_pass<<<12 * 64, 256>>>(data, t, (float*)d_out);
}

// round 11
// speedup vs baseline: 1.1313x; 1.0092x over previous
#include <cuda_runtime.h>
#include <cstdint>

#define MM 2
#define LL 6
#define NN 512
#define HH 64
#define VK 1.0f
#define SIG2 0.01
#define DDIM 2.0
#define NT 8192
#define RMAX 16.0f
#define HSTEP (RMAX / (float)NT)
#define NWARP (MM * LL * NN)      // 6144 i-warps total
#define BNODES 64                 // nodes computed per builder block
#define BSTRIDE 63                // entries emitted per builder block (overlap 1)

typedef unsigned long long u64;

__device__ float4 g_tab[NT];        // (phi, dphi, d2, d2-slope) Taylor entries
__device__ double g_slots[64];
__device__ unsigned g_cnt;

__device__ __forceinline__ float tanh_fast(float x) {
    float y; asm("tanh.approx.f32 %0, %1;" : "=f"(y) : "f"(x)); return y;
}
__device__ __forceinline__ u64 pack2(float x) {
    u64 r; asm("mov.b64 %0, {%1,%1};" : "=l"(r) : "f"(x)); return r;
}
__device__ __forceinline__ u64 pack2f(float lo, float hi) {
    u64 r; asm("mov.b64 %0, {%1,%2};" : "=l"(r) : "f"(lo), "f"(hi)); return r;
}
__device__ __forceinline__ void unpack2(u64 v, float& lo, float& hi) {
    asm("mov.b64 {%0,%1}, %2;" : "=f"(lo), "=f"(hi) : "l"(v));
}
__device__ __forceinline__ u64 fma2(u64 a, u64 b, u64 c) {
    u64 d; asm("fma.rn.f32x2 %0, %1, %2, %3;" : "=l"(d) : "l"(a), "l"(b), "l"(c)); return d;
}

// ------- builder (R8 2-way split) + fused Taylor pack via smem overlap -------
__global__ void __launch_bounds__(128)
build_table(const float* __restrict__ w1, const float* __restrict__ b1,
            const float* __restrict__ W2, const float* __restrict__ b2,
            const float* __restrict__ w3, const float* __restrict__ b3p)
{
    __shared__ float sW2[HH * HH];
    __shared__ float sw1[HH], sb1[HH], sb2[HH], sw3[HH];
    __shared__ float h1s[HH * 64];        // [k][pair]
    __shared__ float sphi[BNODES], sdphi[BNODES], sd2[BNODES];

    int tid = threadIdx.x;
    #pragma unroll
    for (int s = 0; s < HH * HH; s += 128) sW2[s + tid] = W2[s + tid];
    if (tid < HH) { sw1[tid] = w1[tid]; sb1[tid] = b1[tid]; sb2[tid] = b2[tid]; sw3[tid] = w3[tid]; }

    if (blockIdx.x == 0) {
        if (tid < 64) g_slots[tid] = 0.0;
        if (tid == 64) g_cnt = 0u;
    }
    __syncthreads();

    int half = tid & 1;
    int pair = tid >> 1;                     // node slot 0..63
    int ridx = blockIdx.x * BSTRIDE + pair;  // global node id
    float r = (float)ridx * HSTEP;

    int kbase = half * 32;
    #pragma unroll 8
    for (int k = kbase; k < kbase + 32; k++)
        h1s[k * 64 + pair] = tanh_fast(fmaf(r, sw1[k], sb1[k]));
    __syncthreads();

    float phi = 0.f, dphi = 0.f, d2phi = 0.f;

    #pragma unroll
    for (int cc = 0; cc < 2; cc++) {
        int c = half * 32 + cc * 16;
        u64 z2[8], zp[8], zpp[8];
        #pragma unroll
        for (int p = 0; p < 8; p++) {
            z2[p]  = pack2f(sb2[c + 2 * p], sb2[c + 2 * p + 1]);
            zp[p]  = 0ull;
            zpp[p] = 0ull;
        }
        #pragma unroll 8
        for (int k = 0; k < HH; k++) {
            float h   = h1s[k * 64 + pair];
            float w1k = sw1[k];
            float s   = fmaf(-h, h, 1.f);
            float hp  = s * w1k;
            float hpp = -2.f * h * hp * w1k;
            u64 hh   = pack2(h);
            u64 hpx  = pack2(hp);
            u64 hppx = pack2(hpp);
            const ulonglong2* wr = (const ulonglong2*)(sW2 + k * HH + c);
            #pragma unroll
            for (int q = 0; q < 4; q++) {
                ulonglong2 w = wr[q];
                z2[2 * q]      = fma2(w.x, hh,   z2[2 * q]);
                z2[2 * q + 1]  = fma2(w.y, hh,   z2[2 * q + 1]);
                zp[2 * q]      = fma2(w.x, hpx,  zp[2 * q]);
                zp[2 * q + 1]  = fma2(w.y, hpx,  zp[2 * q + 1]);
                zpp[2 * q]     = fma2(w.x, hppx, zpp[2 * q]);
                zpp[2 * q + 1] = fma2(w.y, hppx, zpp[2 * q + 1]);
            }
        }
        #pragma unroll
        for (int p = 0; p < 8; p++) {
            float a0, a1, p0, p1, q0, q1;
            unpack2(z2[p], a0, a1);
            unpack2(zp[p], p0, p1);
            unpack2(zpp[p], q0, q1);
            float w30 = sw3[c + 2 * p], w31 = sw3[c + 2 * p + 1];

            float h2 = tanh_fast(a0);
            phi = fmaf(w30, h2, phi);
            float e   = fmaf(-h2, h2, 1.f);
            float hp2 = e * p0;
            float hq2 = fmaf(e, q0, -2.f * h2 * hp2 * p0);
            dphi  = fmaf(w30, hp2, dphi);
            d2phi = fmaf(w30, hq2, d2phi);

            h2 = tanh_fast(a1);
            phi = fmaf(w31, h2, phi);
            e   = fmaf(-h2, h2, 1.f);
            hp2 = e * p1;
            hq2 = fmaf(e, q1, -2.f * h2 * hp2 * p1);
            dphi  = fmaf(w31, hp2, dphi);
            d2phi = fmaf(w31, hq2, d2phi);
        }
    }

    phi   += __shfl_xor_sync(0xffffffffu, phi,   1);
    dphi  += __shfl_xor_sync(0xffffffffu, dphi,  1);
    d2phi += __shfl_xor_sync(0xffffffffu, d2phi, 1);

    if (half == 0) {
        sphi[pair]  = phi + b3p[0];
        sdphi[pair] = dphi;
        sd2[pair]   = d2phi;
    }
    __syncthreads();

    if (half == 0 && pair < BSTRIDE) {
        int e = blockIdx.x * BSTRIDE + pair;
        if (e < NT)
            g_tab[e] = make_float4(sphi[pair], sdphi[pair], sd2[pair],
                                   sd2[pair + 1] - sd2[pair]);
    }
}

// ------- pair pass: one warp per i, fused final reduction -------
__global__ void __launch_bounds__(256)
pair_pass(const float* __restrict__ data, const float* __restrict__ t,
          float* __restrict__ out)
{
    __shared__ float2 sx[NN];

    int tid  = threadIdx.x;
    int w    = tid >> 5;
    int lane = tid & 31;
    int sl   = blockIdx.x >> 6;          // 0..11
    int i    = (blockIdx.x & 63) * 8 + w;
    int l    = sl % LL;
    int m    = sl / LL;
    bool deriv   = (l < LL - 1);
    bool needphi = (l == 0 || l == LL - 1);

    const float2* snap = (const float2*)(data + ((size_t)(m * LL + l)) * NN * 2);
    sx[tid]       = snap[tid];
    sx[tid + 256] = snap[tid + 256];
    __syncthreads();

    float2 xi = sx[i];
    float gx = 0.f, gy = 0.f, lap = 0.f, phis = 0.f;
    const float scale = (float)NT / RMAX;

    #pragma unroll 8
    for (int jj = 0; jj < 16; jj++) {
        int j = lane + jj * 32;
        float2 xj = sx[j];
        float dx = xi.x - xj.x, dy = xi.y - xj.y;
        float ssq = dx * dx + dy * dy;
        if (j != i) {
            float inv = rsqrtf(fmaxf(ssq, 1e-20f));
            float r = ssq * inv;
            float u = r * scale;
            int i0 = (int)u;
            i0 = (i0 > NT - 2) ? (NT - 2) : i0;
            float f = u - (float)i0;
            float4 e = __ldg(&g_tab[i0]);
            float x  = f * HSTEP;
            float d2 = fmaf(f, e.w, e.z);
            float dp = fmaf(x, fmaf(0.5f * f, e.w, e.z), e.y);
            float ph = fmaf(x, fmaf(0.5f * x, fmaf(0.33333333f * f, e.w, e.z), e.y), e.x);
            phis += ph;
            lap  += d2;
            float c = dp * inv;
            gx = fmaf(c, dx, gx);
            gy = fmaf(c, dy, gy);
        }
    }

    #pragma unroll
    for (int s = 16; s > 0; s >>= 1) {
        gx   += __shfl_xor_sync(0xffffffffu, gx,   s);
        gy   += __shfl_xor_sync(0xffffffffu, gy,   s);
        lap  += __shfl_xor_sync(0xffffffffu, lap,  s);
        phis += __shfl_xor_sync(0xffffffffu, phis, s);
    }

    unsigned old = 0u;
    if (lane == 0) {
        double contrib = 0.0;
        if (deriv) {
            float dtl = t[l + 1] - t[l];
            float dgx = fmaf(-VK, xi.x, -gx / NN);
            float dgy = fmaf(-VK, xi.y, -gy / NN);
            contrib += (double)dtl * ((double)dgx * dgx + (double)dgy * dgy) / NN;
            contrib += SIG2 * (double)dtl * ((double)lap / NN) / NN;
        }
        if (needphi) {
            double sign = (l == 0) ? 2.0 : -2.0;
            contrib += sign * ((double)phis / ((double)NN * NN)
                             + 0.5 * (double)VK * ((double)xi.x * xi.x + (double)xi.y * xi.y) / NN);
        }
        // release-scoped slot add (no CCTL.IVALL / L1 flush, unlike __threadfence)
        asm volatile("red.release.gpu.global.add.f64 [%0], %1;"
                     :: "l"(&g_slots[i & 63]), "d"(contrib) : "memory");
        // acq_rel counter: release publishes the slot add; acquire orders the
        // winner's subsequent slot reads
        asm volatile("atom.acq_rel.gpu.global.add.u32 %0, [%1], %2;"
                     : "=r"(old) : "l"(&g_cnt), "r"(1u) : "memory");
    }
    old = __shfl_sync(0xffffffffu, old, 0);

    if (old == (unsigned)(NWARP - 1)) {
        double s0, s1;
        asm volatile("ld.acquire.gpu.global.f64 %0, [%1];"
                     : "=d"(s0) : "l"(&g_slots[lane]) : "memory");
        asm volatile("ld.acquire.gpu.global.f64 %0, [%1];"
                     : "=d"(s1) : "l"(&g_slots[lane + 32]) : "memory");
        double s = s0 + s1;
        #pragma unroll
        for (int k = 16; k > 0; k >>= 1) {
            double other;
            {
                u64 v = __double_as_longlong(s);
                uint32_t lo = (uint32_t)v, hi = (uint32_t)(v >> 32);
                lo = __shfl_xor_sync(0xffffffffu, lo, k);
                hi = __shfl_xor_sync(0xffffffffu, hi, k);
                other = __longlong_as_double(((u64)hi << 32) | lo);
            }
            s += other;
        }
        if (lane == 0) {
            s += (double)MM * SIG2 * (double)VK * DDIM * (double)(t[LL - 1] - t[0]);
            double res = s / (double)(MM * (LL - 1));
            out[0] = (float)(res * res);
        }
    }
}

extern "C" void kernel_launch(void* const* d_in, const int* in_sizes, int n_in,
                              void* d_out, int out_size)
{
    const float* data = (const float*)d_in[0];
    const float* t    = (const float*)d_in[1];
    const float* w1   = (const float*)d_in[2];
    const float* b1   = (const float*)d_in[3];
    const float* W2   = (const float*)d_in[4];
    const float* b2   = (const float*)d_in[5];
    const float* w3   = (const float*)d_in[6];
    const float* b3   = (const float*)d_in[7];

    int bgrid = (NT + BSTRIDE - 1) / BSTRIDE;   // 131 blocks (overlap by 1 node)
    build_table<<<bgrid, 128>>>(w1, b1, W2, b2, w3, b3);
    pair_pass<<<12 * 64, 256>>>(data, t, (float*)d_out);
}